// round 9
// baseline (speedup 1.0000x reference)
#include <cuda_runtime.h>
#include <cuda_fp16.h>
#include <cuda_bf16.h>
#include <cstdint>

#define N_NODES 50000
#define E_EDGES 800000
#define DIM     256
#define NHEAD   8
#define SCAN_BLK 1024
#define NBLK_SCAN ((N_NODES + SCAN_BLK - 1) / SCAN_BLK)   // 49

// ---------------- device scratch (allocation-free rule: use globals) -------
__device__ float  g_attr_sum[N_NODES * 2];
__device__ int    g_deg[N_NODES];
__device__ float  g_loop_attr[N_NODES * 2];
__device__ __half g_xl_h[(size_t)N_NODES * DIM];   // x @ W_l (fp16)
__device__ __half g_xr_h[(size_t)N_NODES * DIM];   // x @ W_r (fp16)
__device__ int    g_row_start[N_NODES];
__device__ int    g_fill[N_NODES];
__device__ int    g_csr_src[E_EDGES];
__device__ float2 g_csr_ea[E_EDGES];
__device__ int    g_scan_tmp[N_NODES];
__device__ int    g_block_sums[64];
__device__ int    g_block_off[64];
__device__ float  g_x_t[(size_t)N_NODES * DIM];    // x pre-rounded to tf32 bits
__device__ float  g_wl_t[DIM * DIM];
__device__ float  g_wr_t[DIM * DIM];

__device__ __forceinline__ uint32_t f2tf32(float f) {
    uint32_t u;
    asm("cvt.rna.tf32.f32 %0, %1;" : "=r"(u) : "f"(f));
    return u;
}

// ---------------- tf32 pre-round (rna) --------------------------------------
__global__ void cvt_tf32_kernel(const float4* __restrict__ in, float4* __restrict__ out, int n4) {
    int i = blockIdx.x * blockDim.x + threadIdx.x;
    if (i >= n4) return;
    float4 v = in[i];
    v.x = __uint_as_float(f2tf32(v.x));
    v.y = __uint_as_float(f2tf32(v.y));
    v.z = __uint_as_float(f2tf32(v.z));
    v.w = __uint_as_float(f2tf32(v.w));
    out[i] = v;
}

// ---------------- zero accumulators ----------------------------------------
__global__ void zero_kernel() {
    int i = blockIdx.x * blockDim.x + threadIdx.x;
    if (i < N_NODES) {
        g_deg[i] = 0;
        g_attr_sum[2 * i] = 0.f;
        g_attr_sum[2 * i + 1] = 0.f;
    }
}

// ---------------- degree count + scatter-mean of edge_attr by dst ----------
__global__ void edge_stats_kernel(const int* __restrict__ edge_index,
                                  const float* __restrict__ edge_attr) {
    int e = blockIdx.x * blockDim.x + threadIdx.x;
    if (e >= E_EDGES) return;
    int d = edge_index[E_EDGES + e];
    atomicAdd(&g_attr_sum[2 * d],     edge_attr[2 * e]);
    atomicAdd(&g_attr_sum[2 * d + 1], edge_attr[2 * e + 1]);
    atomicAdd(&g_deg[d], 1);
}

// ---------------- 3-phase parallel exclusive scan of degrees ---------------
__global__ __launch_bounds__(SCAN_BLK)
void scan_phase1_kernel() {
    __shared__ int warp_sums[32];
    int tid = threadIdx.x;
    int lane = tid & 31;
    int wid = tid >> 5;
    int idx = blockIdx.x * SCAN_BLK + tid;

    int v = (idx < N_NODES) ? g_deg[idx] : 0;
    int incl = v;
#pragma unroll
    for (int off = 1; off < 32; off <<= 1) {
        int t = __shfl_up_sync(0xffffffffu, incl, off);
        if (lane >= off) incl += t;
    }
    if (lane == 31) warp_sums[wid] = incl;
    __syncthreads();
    if (wid == 0) {
        int w = warp_sums[lane];
        int wi = w;
#pragma unroll
        for (int off = 1; off < 32; off <<= 1) {
            int t = __shfl_up_sync(0xffffffffu, wi, off);
            if (lane >= off) wi += t;
        }
        warp_sums[lane] = wi - w;
        if (lane == 31) g_block_sums[blockIdx.x] = wi;
    }
    __syncthreads();
    if (idx < N_NODES)
        g_scan_tmp[idx] = warp_sums[wid] + incl - v;
}

__global__ void scan_phase2_kernel() {
    int lane = threadIdx.x;
    int v0 = (lane < NBLK_SCAN) ? g_block_sums[lane] : 0;
    int v1 = (lane + 32 < NBLK_SCAN) ? g_block_sums[lane + 32] : 0;

    int i0 = v0;
#pragma unroll
    for (int off = 1; off < 32; off <<= 1) {
        int t = __shfl_up_sync(0xffffffffu, i0, off);
        if (lane >= off) i0 += t;
    }
    int total0 = __shfl_sync(0xffffffffu, i0, 31);

    int i1 = v1;
#pragma unroll
    for (int off = 1; off < 32; off <<= 1) {
        int t = __shfl_up_sync(0xffffffffu, i1, off);
        if (lane >= off) i1 += t;
    }

    if (lane < NBLK_SCAN)      g_block_off[lane]      = i0 - v0;
    if (lane + 32 < NBLK_SCAN) g_block_off[lane + 32] = total0 + i1 - v1;
}

__global__ void scan_phase3_kernel() {
    int i = blockIdx.x * blockDim.x + threadIdx.x;
    if (i >= N_NODES) return;
    int rs = g_scan_tmp[i] + g_block_off[i / SCAN_BLK];
    g_row_start[i] = rs;
    g_fill[i] = rs;
    float c = fmaxf((float)g_deg[i], 1.0f);
    g_loop_attr[2 * i]     = g_attr_sum[2 * i] / c;
    g_loop_attr[2 * i + 1] = g_attr_sum[2 * i + 1] / c;
}

// ---------------- CSR fill ---------------------------------------------------
__global__ void csr_fill_kernel(const int* __restrict__ edge_index,
                                const float* __restrict__ edge_attr) {
    int e = blockIdx.x * blockDim.x + threadIdx.x;
    if (e >= E_EDGES) return;
    int d = edge_index[E_EDGES + e];
    int pos = atomicAdd(&g_fill[d], 1);
    g_csr_src[pos] = edge_index[e];
    g_csr_ea[pos] = make_float2(edge_attr[2 * e], edge_attr[2 * e + 1]);
}

// ============================================================================
// TF32 tensor-core dual GEMM on pre-rounded inputs (no cvt in inner loop)
// ============================================================================
#define GBM 128
#define GBN 128
#define GBK 16
#define AS_STRIDE 20
#define BS_STRIDE 136

__device__ __forceinline__ void mma_tf32(float4& d, const uint32_t* a, const uint32_t* b) {
    asm volatile(
        "mma.sync.aligned.m16n8k8.row.col.f32.tf32.tf32.f32 "
        "{%0,%1,%2,%3}, {%4,%5,%6,%7}, {%8,%9}, {%0,%1,%2,%3};"
        : "+f"(d.x), "+f"(d.y), "+f"(d.z), "+f"(d.w)
        : "r"(a[0]), "r"(a[1]), "r"(a[2]), "r"(a[3]), "r"(b[0]), "r"(b[1]));
}

__device__ __forceinline__ void cp_async16(uint32_t smem_dst, const void* gmem_src, int src_bytes) {
    asm volatile("cp.async.cg.shared.global [%0], [%1], 16, %2;"
                 :: "r"(smem_dst), "l"(gmem_src), "r"(src_bytes));
}
__device__ __forceinline__ void cp_commit() { asm volatile("cp.async.commit_group;"); }
template<int NN> __device__ __forceinline__ void cp_wait() {
    asm volatile("cp.async.wait_group %0;" :: "n"(NN));
}

__global__ __launch_bounds__(256)
void gemm_tf32_kernel(const float* __restrict__ A,
                      const float* __restrict__ Bl,
                      const float* __restrict__ Br,
                      int M) {
    __shared__ float As[2][GBM * AS_STRIDE];
    __shared__ float Bs[2][GBK * BS_STRIDE];

    const int tid  = threadIdx.x;
    const int wid  = tid >> 5;
    const int lane = tid & 31;
    const int g    = lane >> 2;
    const int tg   = lane & 3;

    const int warpM = wid & 1;
    const int warpN = wid >> 1;

    const int bm = blockIdx.x * GBM;
    const int bn = blockIdx.y * GBN;
    const float* B = (blockIdx.z == 0) ? Bl : Br;
    __half* Cout = (blockIdx.z == 0) ? g_xl_h : g_xr_h;

    float4 acc[4][4];
#pragma unroll
    for (int i = 0; i < 4; i++)
#pragma unroll
        for (int j = 0; j < 4; j++) acc[i][j] = make_float4(0.f, 0.f, 0.f, 0.f);

    auto load_tiles = [&](int kt, int st) {
#pragma unroll
        for (int r = 0; r < 2; r++) {
            int f = tid + r * 256;
            int m = f >> 2, kc = f & 3;
            const float* srcA = (bm + m < M) ? &A[(size_t)(bm + m) * DIM + kt + kc * 4]
                                             : &A[(size_t)bm * DIM + kt + kc * 4];
            uint32_t dst = (uint32_t)__cvta_generic_to_shared(&As[st][m * AS_STRIDE + kc * 4]);
            cp_async16(dst, srcA, (bm + m < M) ? 16 : 0);
        }
#pragma unroll
        for (int r = 0; r < 2; r++) {
            int f = tid + r * 256;
            int k = f >> 5, nc = f & 31;
            const float* srcB = &B[(size_t)(kt + k) * DIM + bn + nc * 4];
            uint32_t dst = (uint32_t)__cvta_generic_to_shared(&Bs[st][k * BS_STRIDE + nc * 4]);
            cp_async16(dst, srcB, 16);
        }
        cp_commit();
    };

    const int NITER = DIM / GBK;
    load_tiles(0, 0);

    for (int it = 0; it < NITER; it++) {
        int st = it & 1;
        if (it + 1 < NITER) {
            load_tiles((it + 1) * GBK, st ^ 1);
            cp_wait<1>();
        } else {
            cp_wait<0>();
        }
        __syncthreads();

        const float* as = As[st];
        const float* bs = Bs[st];
#pragma unroll
        for (int ks = 0; ks < 2; ks++) {
            uint32_t af[4][4];
#pragma unroll
            for (int mt = 0; mt < 4; mt++) {
                int m0 = warpM * 64 + mt * 16;
                int k0 = ks * 8 + tg;
                af[mt][0] = __float_as_uint(as[(m0 + g)     * AS_STRIDE + k0]);
                af[mt][1] = __float_as_uint(as[(m0 + g + 8) * AS_STRIDE + k0]);
                af[mt][2] = __float_as_uint(as[(m0 + g)     * AS_STRIDE + k0 + 4]);
                af[mt][3] = __float_as_uint(as[(m0 + g + 8) * AS_STRIDE + k0 + 4]);
            }
            uint32_t bf[4][2];
#pragma unroll
            for (int nt = 0; nt < 4; nt++) {
                int n0 = warpN * 32 + nt * 8 + g;
                bf[nt][0] = __float_as_uint(bs[(ks * 8 + tg)     * BS_STRIDE + n0]);
                bf[nt][1] = __float_as_uint(bs[(ks * 8 + tg + 4) * BS_STRIDE + n0]);
            }
#pragma unroll
            for (int mt = 0; mt < 4; mt++)
#pragma unroll
                for (int nt = 0; nt < 4; nt++)
                    mma_tf32(acc[mt][nt], af[mt], bf[nt]);
        }
        __syncthreads();
    }

#pragma unroll
    for (int mt = 0; mt < 4; mt++) {
        int r0 = bm + warpM * 64 + mt * 16 + g;
        int r1 = r0 + 8;
#pragma unroll
        for (int nt = 0; nt < 4; nt++) {
            int col = bn + warpN * 32 + nt * 8 + tg * 2;
            if (r0 < M)
                *(__half2*)&Cout[(size_t)r0 * DIM + col] = __floats2half2_rn(acc[mt][nt].x, acc[mt][nt].y);
            if (r1 < M)
                *(__half2*)&Cout[(size_t)r1 * DIM + col] = __floats2half2_rn(acc[mt][nt].z, acc[mt][nt].w);
        }
    }
}

// ============================================================================
// node-centric fused pass v2: warp per node, broadcast-index pipeline.
// All neighbor indices/edge_attrs loaded in ONE coalesced load per 32-edge
// chunk (lane i -> edge i), then shfl-broadcast per iteration. xl gathers
// double-buffered. No atomics.
// ============================================================================
__global__ __launch_bounds__(256)
void node_fused_kernel(const float* __restrict__ W_e,
                       const float* __restrict__ att,
                       const float* __restrict__ bias,
                       float* __restrict__ out) {
    __shared__ float sWe0[DIM];
    __shared__ float sWe1[DIM];
    __shared__ float sAtt[DIM];
    __shared__ float sBias[DIM];
    for (int i = threadIdx.x; i < DIM; i += blockDim.x) {
        sWe0[i] = W_e[i];
        sWe1[i] = W_e[DIM + i];
        sAtt[i] = att[i];
        sBias[i] = bias[i];
    }
    __syncthreads();

    int warp = (int)((blockIdx.x * (size_t)blockDim.x + threadIdx.x) >> 5);
    int lane = threadIdx.x & 31;
    if (warp >= N_NODES) return;
    int n = warp;
    int ch0 = lane * 8;

    float xr[8];
    {
        uint4 rv = *(const uint4*)&g_xr_h[(size_t)n * DIM + ch0];
        const __half2* rh = (const __half2*)&rv;
#pragma unroll
        for (int j = 0; j < 4; j++) {
            float2 f = __half22float2(rh[j]);
            xr[2 * j] = f.x; xr[2 * j + 1] = f.y;
        }
    }

    float we0[8], we1[8], av[8];
#pragma unroll
    for (int j = 0; j < 8; j++) {
        we0[j] = sWe0[ch0 + j];
        we1[j] = sWe1[ch0 + j];
        av[j]  = sAtt[ch0 + j];
    }

    float acc[8] = {0.f, 0.f, 0.f, 0.f, 0.f, 0.f, 0.f, 0.f};
    float denom = 0.f;

    int row = g_row_start[n];
    int deg = g_deg[n];

    // ---- self loop ----
    {
        float ea0 = g_loop_attr[2 * n];
        float ea1 = g_loop_attr[2 * n + 1];
        uint4 lv = *(const uint4*)&g_xl_h[(size_t)n * DIM + ch0];
        const __half2* lh = (const __half2*)&lv;
        float xl[8];
#pragma unroll
        for (int j = 0; j < 4; j++) {
            float2 f = __half22float2(lh[j]);
            xl[2 * j] = f.x; xl[2 * j + 1] = f.y;
        }
        float p = 0.f;
#pragma unroll
        for (int j = 0; j < 8; j++) {
            float m = xl[j] + xr[j] + ea0 * we0[j] + ea1 * we1[j];
            m = (m > 0.f) ? m : 0.2f * m;
            p += m * av[j];
        }
        p += __shfl_xor_sync(0xffffffffu, p, 1);
        p += __shfl_xor_sync(0xffffffffu, p, 2);
        float ex = __expf(p);
        denom += ex;
#pragma unroll
        for (int j = 0; j < 8; j++) acc[j] += ex * xl[j];
    }

    // ---- neighbor chunks of 32 edges (deg ~ Poisson(16)) ----
    for (int base = 0; base < deg; base += 32) {
        int cnt = min(32, deg - base);
        // one coalesced load of this chunk's indices + edge attrs
        int   my_src = 0;
        float2 my_ea = make_float2(0.f, 0.f);
        if (lane < cnt) {
            my_src = g_csr_src[row + base + lane];
            my_ea  = g_csr_ea[row + base + lane];
        }

        // depth-2 pipelined gathers, indices via shfl (no index-load chain)
        uint4 buf0, buf1;
        {
            int s0 = __shfl_sync(0xffffffffu, my_src, 0);
            buf0 = *(const uint4*)&g_xl_h[(size_t)s0 * DIM + ch0];
        }
        if (cnt > 1) {
            int s1 = __shfl_sync(0xffffffffu, my_src, 1);
            buf1 = *(const uint4*)&g_xl_h[(size_t)s1 * DIM + ch0];
        }

        for (int j = 0; j < cnt; j++) {
            uint4 cur = (j & 1) ? buf1 : buf0;
            if (j + 2 < cnt) {
                int sn = __shfl_sync(0xffffffffu, my_src, j + 2);
                uint4 nx = *(const uint4*)&g_xl_h[(size_t)sn * DIM + ch0];
                if (j & 1) buf1 = nx; else buf0 = nx;
            }
            float ea0 = __shfl_sync(0xffffffffu, my_ea.x, j);
            float ea1 = __shfl_sync(0xffffffffu, my_ea.y, j);

            const __half2* lh = (const __half2*)&cur;
            float xl[8];
#pragma unroll
            for (int q = 0; q < 4; q++) {
                float2 f = __half22float2(lh[q]);
                xl[2 * q] = f.x; xl[2 * q + 1] = f.y;
            }
            float p = 0.f;
#pragma unroll
            for (int q = 0; q < 8; q++) {
                float m = xl[q] + xr[q] + ea0 * we0[q] + ea1 * we1[q];
                m = (m > 0.f) ? m : 0.2f * m;   // leaky relu
                p += m * av[q];
            }
            p += __shfl_xor_sync(0xffffffffu, p, 1);
            p += __shfl_xor_sync(0xffffffffu, p, 2);

            float ex = __expf(p);
            denom += ex;
#pragma unroll
            for (int q = 0; q < 8; q++) acc[q] += ex * xl[q];
        }
    }

    float inv = 1.0f / denom;
    float4 o0 = make_float4(acc[0] * inv + sBias[ch0 + 0], acc[1] * inv + sBias[ch0 + 1],
                            acc[2] * inv + sBias[ch0 + 2], acc[3] * inv + sBias[ch0 + 3]);
    float4 o1 = make_float4(acc[4] * inv + sBias[ch0 + 4], acc[5] * inv + sBias[ch0 + 5],
                            acc[6] * inv + sBias[ch0 + 6], acc[7] * inv + sBias[ch0 + 7]);
    *(float4*)&out[(size_t)n * DIM + ch0]     = o0;
    *(float4*)&out[(size_t)n * DIM + ch0 + 4] = o1;
}

// ---------------- launch: fork GEMM branch onto a side stream ---------------
extern "C" void kernel_launch(void* const* d_in, const int* in_sizes, int n_in,
                              void* d_out, int out_size) {
    const float* x          = (const float*)d_in[0];
    const int*   edge_index = (const int*)  d_in[1];
    const float* edge_attr  = (const float*)d_in[2];
    const float* W_l        = (const float*)d_in[3];
    const float* W_r        = (const float*)d_in[4];
    const float* W_e        = (const float*)d_in[5];
    const float* att        = (const float*)d_in[6];
    const float* bias       = (const float*)d_in[7];
    float* out = (float*)d_out;

    cudaStream_t s1;
    cudaStreamCreateWithFlags(&s1, cudaStreamNonBlocking);
    cudaEvent_t ev_fork, ev_gemm;
    cudaEventCreateWithFlags(&ev_fork, cudaEventDisableTiming);
    cudaEventCreateWithFlags(&ev_gemm, cudaEventDisableTiming);

    // fork
    cudaEventRecord(ev_fork, 0);
    cudaStreamWaitEvent(s1, ev_fork, 0);

    // branch A (side stream): tf32 pre-round + dual GEMM
    float* x_t;  cudaGetSymbolAddress((void**)&x_t,  g_x_t);
    float* wl_t; cudaGetSymbolAddress((void**)&wl_t, g_wl_t);
    float* wr_t; cudaGetSymbolAddress((void**)&wr_t, g_wr_t);
    int n4_x = N_NODES * DIM / 4;
    int n4_w = DIM * DIM / 4;
    cvt_tf32_kernel<<<(n4_x + 255) / 256, 256, 0, s1>>>((const float4*)x,   (float4*)x_t,  n4_x);
    cvt_tf32_kernel<<<(n4_w + 255) / 256, 256, 0, s1>>>((const float4*)W_l, (float4*)wl_t, n4_w);
    cvt_tf32_kernel<<<(n4_w + 255) / 256, 256, 0, s1>>>((const float4*)W_r, (float4*)wr_t, n4_w);
    dim3 ggrid((N_NODES + GBM - 1) / GBM, DIM / GBN, 2);
    gemm_tf32_kernel<<<ggrid, 256, 0, s1>>>(x_t, wl_t, wr_t, N_NODES);
    cudaEventRecord(ev_gemm, s1);

    // branch B (capture stream): CSR build
    zero_kernel<<<(N_NODES + 255) / 256, 256>>>();
    edge_stats_kernel<<<(E_EDGES + 255) / 256, 256>>>(edge_index, edge_attr);
    scan_phase1_kernel<<<NBLK_SCAN, SCAN_BLK>>>();
    scan_phase2_kernel<<<1, 32>>>();
    scan_phase3_kernel<<<(N_NODES + 255) / 256, 256>>>();
    csr_fill_kernel<<<(E_EDGES + 255) / 256, 256>>>(edge_index, edge_attr);

    // join
    cudaStreamWaitEvent(0, ev_gemm, 0);

    int nblk = (N_NODES + 7) / 8;   // 8 warps per block
    node_fused_kernel<<<nblk, 256>>>(W_e, att, bias, out);
}

// round 10
// speedup vs baseline: 1.2864x; 1.2864x over previous
#include <cuda_runtime.h>
#include <cuda_fp16.h>
#include <cuda_bf16.h>
#include <cstdint>

#define N_NODES 50000
#define E_EDGES 800000
#define DIM     256
#define NHEAD   8
#define SCAN_BLK 1024
#define NBLK_SCAN ((N_NODES + SCAN_BLK - 1) / SCAN_BLK)   // 49

// ---------------- device scratch (allocation-free rule: use globals) -------
__device__ float  g_attr_sum[N_NODES * 2];
__device__ int    g_deg[N_NODES];
__device__ float  g_loop_attr[N_NODES * 2];
__device__ __half g_xl_h[(size_t)N_NODES * DIM];   // x @ W_l (fp16)
__device__ __half g_xr_h[(size_t)N_NODES * DIM];   // x @ W_r (fp16)
__device__ int    g_row_start[N_NODES];
__device__ int    g_fill[N_NODES];
__device__ int    g_csr_src[E_EDGES];
__device__ float2 g_csr_ea[E_EDGES];
__device__ int    g_scan_tmp[N_NODES];
__device__ int    g_block_sums[64];
__device__ int    g_block_off[64];
__device__ __half g_x_h[(size_t)N_NODES * DIM];    // x in fp16
__device__ __half g_wl_ht[DIM * DIM];              // W_l^T in fp16 [n][k]
__device__ __half g_wr_ht[DIM * DIM];              // W_r^T in fp16 [n][k]

// ---------------- fp32 -> fp16 conversion kernels ---------------------------
__global__ void cvt_half_kernel(const float4* __restrict__ in, __half* __restrict__ out, int n4) {
    int i = blockIdx.x * blockDim.x + threadIdx.x;
    if (i >= n4) return;
    float4 v = in[i];
    __half2 h0 = __floats2half2_rn(v.x, v.y);
    __half2 h1 = __floats2half2_rn(v.z, v.w);
    __half2* o = (__half2*)&out[4 * (size_t)i];
    o[0] = h0; o[1] = h1;
}

// transpose-convert W[k][n] fp32 -> Wt[n][k] fp16
__global__ void cvt_wt_kernel(const float* __restrict__ W, __half* __restrict__ Wt) {
    int i = blockIdx.x * blockDim.x + threadIdx.x;   // output index
    if (i >= DIM * DIM) return;
    int n = i >> 8, k = i & 255;
    Wt[i] = __float2half_rn(W[k * DIM + n]);
}

// ---------------- zero accumulators ----------------------------------------
__global__ void zero_kernel() {
    int i = blockIdx.x * blockDim.x + threadIdx.x;
    if (i < N_NODES) {
        g_deg[i] = 0;
        g_attr_sum[2 * i] = 0.f;
        g_attr_sum[2 * i + 1] = 0.f;
    }
}

// ---------------- degree count + scatter-mean of edge_attr by dst ----------
__global__ void edge_stats_kernel(const int* __restrict__ edge_index,
                                  const float* __restrict__ edge_attr) {
    int e = blockIdx.x * blockDim.x + threadIdx.x;
    if (e >= E_EDGES) return;
    int d = edge_index[E_EDGES + e];
    atomicAdd(&g_attr_sum[2 * d],     edge_attr[2 * e]);
    atomicAdd(&g_attr_sum[2 * d + 1], edge_attr[2 * e + 1]);
    atomicAdd(&g_deg[d], 1);
}

// ---------------- 3-phase parallel exclusive scan of degrees ---------------
__global__ __launch_bounds__(SCAN_BLK)
void scan_phase1_kernel() {
    __shared__ int warp_sums[32];
    int tid = threadIdx.x;
    int lane = tid & 31;
    int wid = tid >> 5;
    int idx = blockIdx.x * SCAN_BLK + tid;

    int v = (idx < N_NODES) ? g_deg[idx] : 0;
    int incl = v;
#pragma unroll
    for (int off = 1; off < 32; off <<= 1) {
        int t = __shfl_up_sync(0xffffffffu, incl, off);
        if (lane >= off) incl += t;
    }
    if (lane == 31) warp_sums[wid] = incl;
    __syncthreads();
    if (wid == 0) {
        int w = warp_sums[lane];
        int wi = w;
#pragma unroll
        for (int off = 1; off < 32; off <<= 1) {
            int t = __shfl_up_sync(0xffffffffu, wi, off);
            if (lane >= off) wi += t;
        }
        warp_sums[lane] = wi - w;
        if (lane == 31) g_block_sums[blockIdx.x] = wi;
    }
    __syncthreads();
    if (idx < N_NODES)
        g_scan_tmp[idx] = warp_sums[wid] + incl - v;
}

__global__ void scan_phase2_kernel() {
    int lane = threadIdx.x;
    int v0 = (lane < NBLK_SCAN) ? g_block_sums[lane] : 0;
    int v1 = (lane + 32 < NBLK_SCAN) ? g_block_sums[lane + 32] : 0;

    int i0 = v0;
#pragma unroll
    for (int off = 1; off < 32; off <<= 1) {
        int t = __shfl_up_sync(0xffffffffu, i0, off);
        if (lane >= off) i0 += t;
    }
    int total0 = __shfl_sync(0xffffffffu, i0, 31);

    int i1 = v1;
#pragma unroll
    for (int off = 1; off < 32; off <<= 1) {
        int t = __shfl_up_sync(0xffffffffu, i1, off);
        if (lane >= off) i1 += t;
    }

    if (lane < NBLK_SCAN)      g_block_off[lane]      = i0 - v0;
    if (lane + 32 < NBLK_SCAN) g_block_off[lane + 32] = total0 + i1 - v1;
}

__global__ void scan_phase3_kernel() {
    int i = blockIdx.x * blockDim.x + threadIdx.x;
    if (i >= N_NODES) return;
    int rs = g_scan_tmp[i] + g_block_off[i / SCAN_BLK];
    g_row_start[i] = rs;
    g_fill[i] = rs;
    float c = fmaxf((float)g_deg[i], 1.0f);
    g_loop_attr[2 * i]     = g_attr_sum[2 * i] / c;
    g_loop_attr[2 * i + 1] = g_attr_sum[2 * i + 1] / c;
}

// ---------------- CSR fill ---------------------------------------------------
__global__ void csr_fill_kernel(const int* __restrict__ edge_index,
                                const float* __restrict__ edge_attr) {
    int e = blockIdx.x * blockDim.x + threadIdx.x;
    if (e >= E_EDGES) return;
    int d = edge_index[E_EDGES + e];
    int pos = atomicAdd(&g_fill[d], 1);
    g_csr_src[pos] = edge_index[e];
    g_csr_ea[pos] = make_float2(edge_attr[2 * e], edge_attr[2 * e + 1]);
}

// ============================================================================
// FP16 tensor-core dual GEMM: xl = x@W_l (z=0), xr = x@W_r (z=1), fp16 out.
// A = x_h [M][256] half (row-major). B = W^T [n][k] half.
// BM=128, BN=128, BK=32 halves. Smem pitch 40 halves (80B): 16B-aligned for
// cp.async, conflict-free (bank = 20g+tg mod 32, all distinct).
// mma.m16n8k16.f16: half the MMA count of tf32 k8.
// ============================================================================
#define GBM 128
#define GBN 128
#define GBK 32
#define PITCH 40

__device__ __forceinline__ void mma_f16(float4& d, const uint32_t* a, const uint32_t* b) {
    asm volatile(
        "mma.sync.aligned.m16n8k16.row.col.f32.f16.f16.f32 "
        "{%0,%1,%2,%3}, {%4,%5,%6,%7}, {%8,%9}, {%0,%1,%2,%3};"
        : "+f"(d.x), "+f"(d.y), "+f"(d.z), "+f"(d.w)
        : "r"(a[0]), "r"(a[1]), "r"(a[2]), "r"(a[3]), "r"(b[0]), "r"(b[1]));
}

__device__ __forceinline__ void cp_async16(uint32_t smem_dst, const void* gmem_src, int src_bytes) {
    asm volatile("cp.async.cg.shared.global [%0], [%1], 16, %2;"
                 :: "r"(smem_dst), "l"(gmem_src), "r"(src_bytes));
}
__device__ __forceinline__ void cp_commit() { asm volatile("cp.async.commit_group;"); }
template<int NN> __device__ __forceinline__ void cp_wait() {
    asm volatile("cp.async.wait_group %0;" :: "n"(NN));
}

__global__ __launch_bounds__(256)
void gemm_f16_kernel(const __half* __restrict__ A,
                     const __half* __restrict__ Bl,
                     const __half* __restrict__ Br,
                     int M) {
    __shared__ __half As[2][GBM * PITCH];
    __shared__ __half Bs[2][GBN * PITCH];

    const int tid  = threadIdx.x;
    const int wid  = tid >> 5;
    const int lane = tid & 31;
    const int g    = lane >> 2;      // 0..7
    const int tg   = lane & 3;       // 0..3

    const int warpM = wid & 1;       // m offset 0/64
    const int warpN = wid >> 1;      // n offset 0/32/64/96

    const int bm = blockIdx.x * GBM;
    const int bn = blockIdx.y * GBN;
    const __half* B = (blockIdx.z == 0) ? Bl : Br;
    __half* Cout = (blockIdx.z == 0) ? g_xl_h : g_xr_h;

    float4 acc[4][4];
#pragma unroll
    for (int i = 0; i < 4; i++)
#pragma unroll
        for (int j = 0; j < 4; j++) acc[i][j] = make_float4(0.f, 0.f, 0.f, 0.f);

    // tile loader: 128 rows x 32 halves (64B) = 4 chunks/row, 512 chunks, 2/thread
    auto load_tiles = [&](int kt, int st) {
#pragma unroll
        for (int r = 0; r < 2; r++) {
            int f = tid + r * 256;
            int row = f >> 2, c = f & 3;      // c*8 halves = c*16 bytes
            const __half* srcA = (bm + row < M) ? &A[(size_t)(bm + row) * DIM + kt + c * 8]
                                                : &A[(size_t)bm * DIM + kt + c * 8];
            uint32_t dstA = (uint32_t)__cvta_generic_to_shared(&As[st][row * PITCH + c * 8]);
            cp_async16(dstA, srcA, (bm + row < M) ? 16 : 0);

            const __half* srcB = &B[(size_t)(bn + row) * DIM + kt + c * 8];
            uint32_t dstB = (uint32_t)__cvta_generic_to_shared(&Bs[st][row * PITCH + c * 8]);
            cp_async16(dstB, srcB, 16);
        }
        cp_commit();
    };

    const int NITER = DIM / GBK;   // 8
    load_tiles(0, 0);

    for (int it = 0; it < NITER; it++) {
        int st = it & 1;
        if (it + 1 < NITER) {
            load_tiles((it + 1) * GBK, st ^ 1);
            cp_wait<1>();
        } else {
            cp_wait<0>();
        }
        __syncthreads();

        const __half* as = As[st];
        const __half* bs = Bs[st];
#pragma unroll
        for (int ks = 0; ks < 2; ks++) {
            int k0 = ks * 16;
            uint32_t af[4][4];
#pragma unroll
            for (int mt = 0; mt < 4; mt++) {
                int m0 = warpM * 64 + mt * 16;
                int base = (m0 + g) * PITCH + k0 + 2 * tg;
                af[mt][0] = *(const uint32_t*)&as[base];
                af[mt][1] = *(const uint32_t*)&as[base + 8 * PITCH];
                af[mt][2] = *(const uint32_t*)&as[base + 8];
                af[mt][3] = *(const uint32_t*)&as[base + 8 * PITCH + 8];
            }
            uint32_t bf[4][2];
#pragma unroll
            for (int nt = 0; nt < 4; nt++) {
                int n0 = warpN * 32 + nt * 8 + g;
                int bbase = n0 * PITCH + k0 + 2 * tg;
                bf[nt][0] = *(const uint32_t*)&bs[bbase];
                bf[nt][1] = *(const uint32_t*)&bs[bbase + 8];
            }
#pragma unroll
            for (int mt = 0; mt < 4; mt++)
#pragma unroll
                for (int nt = 0; nt < 4; nt++)
                    mma_f16(acc[mt][nt], af[mt], bf[nt]);
        }
        __syncthreads();
    }

#pragma unroll
    for (int mt = 0; mt < 4; mt++) {
        int r0 = bm + warpM * 64 + mt * 16 + g;
        int r1 = r0 + 8;
#pragma unroll
        for (int nt = 0; nt < 4; nt++) {
            int col = bn + warpN * 32 + nt * 8 + tg * 2;
            if (r0 < M)
                *(__half2*)&Cout[(size_t)r0 * DIM + col] = __floats2half2_rn(acc[mt][nt].x, acc[mt][nt].y);
            if (r1 < M)
                *(__half2*)&Cout[(size_t)r1 * DIM + col] = __floats2half2_rn(acc[mt][nt].z, acc[mt][nt].w);
        }
    }
}

// ============================================================================
// node-centric fused pass (R8 v1): warp per node, depth-1 prefetch. No atomics.
// ============================================================================
__global__ __launch_bounds__(256)
void node_fused_kernel(const float* __restrict__ W_e,
                       const float* __restrict__ att,
                       const float* __restrict__ bias,
                       float* __restrict__ out) {
    __shared__ float sWe0[DIM];
    __shared__ float sWe1[DIM];
    __shared__ float sAtt[DIM];
    __shared__ float sBias[DIM];
    for (int i = threadIdx.x; i < DIM; i += blockDim.x) {
        sWe0[i] = W_e[i];
        sWe1[i] = W_e[DIM + i];
        sAtt[i] = att[i];
        sBias[i] = bias[i];
    }
    __syncthreads();

    int warp = (int)((blockIdx.x * (size_t)blockDim.x + threadIdx.x) >> 5);
    int lane = threadIdx.x & 31;
    if (warp >= N_NODES) return;
    int n = warp;
    int ch0 = lane * 8;

    float xr[8];
    {
        uint4 rv = *(const uint4*)&g_xr_h[(size_t)n * DIM + ch0];
        const __half2* rh = (const __half2*)&rv;
#pragma unroll
        for (int j = 0; j < 4; j++) {
            float2 f = __half22float2(rh[j]);
            xr[2 * j] = f.x; xr[2 * j + 1] = f.y;
        }
    }

    float we0[8], we1[8], av[8];
#pragma unroll
    for (int j = 0; j < 8; j++) {
        we0[j] = sWe0[ch0 + j];
        we1[j] = sWe1[ch0 + j];
        av[j]  = sAtt[ch0 + j];
    }

    float acc[8] = {0.f, 0.f, 0.f, 0.f, 0.f, 0.f, 0.f, 0.f};
    float denom = 0.f;

    int row = g_row_start[n];
    int deg = g_deg[n];

    float ea0_cur = g_loop_attr[2 * n];
    float ea1_cur = g_loop_attr[2 * n + 1];
    uint4 lv_cur  = *(const uint4*)&g_xl_h[(size_t)n * DIM + ch0];

    for (int i = 0; i <= deg; i++) {
        int src_nxt = 0; float ea0_nxt = 0.f, ea1_nxt = 0.f; uint4 lv_nxt;
        bool have_next = (i < deg);
        if (have_next) {
            src_nxt = g_csr_src[row + i];
            float2 ea = g_csr_ea[row + i];
            ea0_nxt = ea.x; ea1_nxt = ea.y;
            lv_nxt = *(const uint4*)&g_xl_h[(size_t)src_nxt * DIM + ch0];
        }

        float xl[8];
        {
            const __half2* lh = (const __half2*)&lv_cur;
#pragma unroll
            for (int j = 0; j < 4; j++) {
                float2 f = __half22float2(lh[j]);
                xl[2 * j] = f.x; xl[2 * j + 1] = f.y;
            }
        }
        float p = 0.f;
#pragma unroll
        for (int j = 0; j < 8; j++) {
            float m = xl[j] + xr[j] + ea0_cur * we0[j] + ea1_cur * we1[j];
            m = (m > 0.f) ? m : 0.2f * m;       // leaky relu
            p += m * av[j];
        }
        p += __shfl_xor_sync(0xffffffffu, p, 1);
        p += __shfl_xor_sync(0xffffffffu, p, 2);

        float ex = __expf(p);
        denom += ex;
#pragma unroll
        for (int j = 0; j < 8; j++) acc[j] += ex * xl[j];

        ea0_cur = ea0_nxt; ea1_cur = ea1_nxt; lv_cur = lv_nxt;
    }

    float inv = 1.0f / denom;
    float4 o0 = make_float4(acc[0] * inv + sBias[ch0 + 0], acc[1] * inv + sBias[ch0 + 1],
                            acc[2] * inv + sBias[ch0 + 2], acc[3] * inv + sBias[ch0 + 3]);
    float4 o1 = make_float4(acc[4] * inv + sBias[ch0 + 4], acc[5] * inv + sBias[ch0 + 5],
                            acc[6] * inv + sBias[ch0 + 6], acc[7] * inv + sBias[ch0 + 7]);
    *(float4*)&out[(size_t)n * DIM + ch0]     = o0;
    *(float4*)&out[(size_t)n * DIM + ch0 + 4] = o1;
}

// ---------------- launch: fork GEMM branch onto a side stream ---------------
extern "C" void kernel_launch(void* const* d_in, const int* in_sizes, int n_in,
                              void* d_out, int out_size) {
    const float* x          = (const float*)d_in[0];
    const int*   edge_index = (const int*)  d_in[1];
    const float* edge_attr  = (const float*)d_in[2];
    const float* W_l        = (const float*)d_in[3];
    const float* W_r        = (const float*)d_in[4];
    const float* W_e        = (const float*)d_in[5];
    const float* att        = (const float*)d_in[6];
    const float* bias       = (const float*)d_in[7];
    float* out = (float*)d_out;

    cudaStream_t s1;
    cudaStreamCreateWithFlags(&s1, cudaStreamNonBlocking);
    cudaEvent_t ev_fork, ev_gemm;
    cudaEventCreateWithFlags(&ev_fork, cudaEventDisableTiming);
    cudaEventCreateWithFlags(&ev_gemm, cudaEventDisableTiming);

    // fork
    cudaEventRecord(ev_fork, 0);
    cudaStreamWaitEvent(s1, ev_fork, 0);

    // branch A (side stream): fp16 convert + dual GEMM
    __half* x_h;  cudaGetSymbolAddress((void**)&x_h,  g_x_h);
    __half* wl_h; cudaGetSymbolAddress((void**)&wl_h, g_wl_ht);
    __half* wr_h; cudaGetSymbolAddress((void**)&wr_h, g_wr_ht);
    int n4_x = N_NODES * DIM / 4;
    cvt_half_kernel<<<(n4_x + 255) / 256, 256, 0, s1>>>((const float4*)x, x_h, n4_x);
    cvt_wt_kernel<<<(DIM * DIM + 255) / 256, 256, 0, s1>>>(W_l, wl_h);
    cvt_wt_kernel<<<(DIM * DIM + 255) / 256, 256, 0, s1>>>(W_r, wr_h);
    dim3 ggrid((N_NODES + GBM - 1) / GBM, DIM / GBN, 2);
    gemm_f16_kernel<<<ggrid, 256, 0, s1>>>(x_h, wl_h, wr_h, N_NODES);
    cudaEventRecord(ev_gemm, s1);

    // branch B (capture stream): CSR build
    zero_kernel<<<(N_NODES + 255) / 256, 256>>>();
    edge_stats_kernel<<<(E_EDGES + 255) / 256, 256>>>(edge_index, edge_attr);
    scan_phase1_kernel<<<NBLK_SCAN, SCAN_BLK>>>();
    scan_phase2_kernel<<<1, 32>>>();
    scan_phase3_kernel<<<(N_NODES + 255) / 256, 256>>>();
    csr_fill_kernel<<<(E_EDGES + 255) / 256, 256>>>(edge_index, edge_attr);

    // join
    cudaStreamWaitEvent(0, ev_gemm, 0);

    int nblk = (N_NODES + 7) / 8;   // 8 warps per block
    node_fused_kernel<<<nblk, 256>>>(W_e, att, bias, out);
}